// round 4
// baseline (speedup 1.0000x reference)
#include <cuda_runtime.h>
#include <cuda_bf16.h>
#include <math.h>

// Problem constants
#define BB 4
#define CC 32
#define WW 256
#define HH 256
#define KK 9
#define OC_OFF 10
#define PIX (WW*HH)

// Main-kernel tile (512 threads: 16 w-rows x 32 h-cols)
#define TW 16
#define TH 32
#define RROWS 26           // TW + 10
#define CCOLS 42           // TH + 10
#define XSZ (CC*RROWS*CCOLS)
#define WSZ (KK*CC*CC)

typedef unsigned long long u64;

__device__ __forceinline__ u64 ffma2(u64 a, u64 b, u64 c) {
    u64 d;
    asm("fma.rn.f32x2 %0, %1, %2, %3;" : "=l"(d) : "l"(a), "l"(b), "l"(c));
    return d;
}
__device__ __forceinline__ u64 pack2(float v) {
    u64 d; unsigned u = __float_as_uint(v);
    asm("mov.b64 %0, {%1, %1};" : "=l"(d) : "r"(u));
    return d;
}
__device__ __forceinline__ void unpack2(u64 in, float& lo, float& hi) {
    unsigned a, b;
    asm("mov.b64 {%0, %1}, %2;" : "=r"(a), "=r"(b) : "l"(in));
    lo = __uint_as_float(a); hi = __uint_as_float(b);
}

// Scratch
__device__ float g_off[BB*OC_OFF*PIX];
__device__ float g_py [BB*KK*PIX];
__device__ float g_pre[BB*CC*PIX];
__device__ float g_soff[BB*5*2];
__device__ float g_mroff[BB*5*2];
__device__ float g_sout[BB*8*2];
__device__ float g_mrout[BB*8*2];

// ---------------------------------------------------------------- zero stats
__global__ void k_zero() {
    int t = threadIdx.x;
    if (t < BB*5*2) g_soff[t] = 0.f;
    if (t < BB*8*2) g_sout[t] = 0.f;
}

// ------------------------------------------------- K1: 3x3 conv, 32 -> 10 ch
// weights padded to 12 per tap -> 3x LDS.128 per tap
__global__ void k_conv_off(const float* __restrict__ x,
                           const float* __restrict__ w_off,
                           const float* __restrict__ b_off) {
    __shared__ __align__(16) float ws[CC*9*12];   // [ci][tap][12]
    __shared__ float s_sum[5], s_sq[5];
    int b   = blockIdx.y;
    int tid = threadIdx.x;

    for (int i = tid; i < CC*9*12; i += 256) {
        int o = i % 12; int rest = i / 12;
        int tap = rest % 9; int ci = rest / 9;
        int dy = tap / 3, dx = tap % 3;
        ws[i] = (o < OC_OFF) ? w_off[((o*CC + ci)*3 + dy)*3 + dx] : 0.f;
    }
    if (tid < 5) { s_sum[tid] = 0.f; s_sq[tid] = 0.f; }
    __syncthreads();

    int p = blockIdx.x*256 + tid;
    int w = p >> 8, h = p & 255;

    u64 acc[6];
    const u64* b2 = (const u64*)b_off;
#pragma unroll
    for (int j = 0; j < 5; j++) acc[j] = b2[j];
    acc[5] = 0ull;

    const float* xb = x + b*CC*PIX;
#pragma unroll 1
    for (int ci = 0; ci < CC; ci++) {
        const float* xc = xb + ci*PIX;
#pragma unroll
        for (int dy = -1; dy <= 1; dy++) {
            int r = w + dy;
            bool rok = (unsigned)r < 256u;
#pragma unroll
            for (int dx = -1; dx <= 1; dx++) {
                int c = h + dx;
                float v = (rok && (unsigned)c < 256u) ? xc[r*256 + c] : 0.f;
                u64 v2 = pack2(v);
                const ulonglong2* wp =
                    (const ulonglong2*)&ws[(ci*9 + (dy+1)*3 + (dx+1))*12];
                ulonglong2 wa = wp[0], wb = wp[1], wc = wp[2];
                acc[0] = ffma2(v2, wa.x, acc[0]);
                acc[1] = ffma2(v2, wa.y, acc[1]);
                acc[2] = ffma2(v2, wb.x, acc[2]);
                acc[3] = ffma2(v2, wb.y, acc[3]);
                acc[4] = ffma2(v2, wc.x, acc[4]);
                acc[5] = ffma2(v2, wc.y, acc[5]);
            }
        }
    }

    float* outp = g_off + b*OC_OFF*PIX + p;
#pragma unroll
    for (int j = 0; j < 5; j++) {
        float v0, v1; unpack2(acc[j], v0, v1);
        outp[(2*j)*PIX]   = v0;
        outp[(2*j+1)*PIX] = v1;
        float s = v0 + v1, q = v0*v0 + v1*v1;
#pragma unroll
        for (int off = 16; off; off >>= 1) {
            s += __shfl_xor_sync(0xffffffffu, s, off);
            q += __shfl_xor_sync(0xffffffffu, q, off);
        }
        if ((tid & 31) == 0) { atomicAdd(&s_sum[j], s); atomicAdd(&s_sq[j], q); }
    }
    __syncthreads();
    if (tid < 5) {
        atomicAdd(&g_soff[(b*5 + tid)*2 + 0], s_sum[tid]);
        atomicAdd(&g_soff[(b*5 + tid)*2 + 1], s_sq[tid]);
    }
}

// --------------------------------------------- K2a: finalize offset GN stats
__global__ void k_stats_off() {
    int t = threadIdx.x;
    if (t < BB*5) {
        float S = g_soff[t*2], Q = g_soff[t*2 + 1];
        float inv = 1.f / (2.f * (float)PIX);
        float mu  = S * inv;
        float var = Q * inv - mu*mu;
        g_mroff[t*2]     = mu;
        g_mroff[t*2 + 1] = rsqrtf(var + 1e-5f);
    }
}

// --------------------- K3: GN + tanh + cumsum -> sampling coordinate field py
__global__ void k_py(const float* __restrict__ sc, const float* __restrict__ bi) {
    int b = blockIdx.y;
    int p = blockIdx.x*256 + threadIdx.x;
    int w = p >> 8;

    float t[9];
#pragma unroll
    for (int c = 0; c < 9; c++) {
        float v  = g_off[(b*OC_OFF + c)*PIX + p];
        int   g  = c >> 1;
        float mu = g_mroff[(b*5 + g)*2], rs = g_mroff[(b*5 + g)*2 + 1];
        t[c] = tanhf(fmaf((v - mu)*rs, sc[c], bi[c]));
    }
    float yc[9];
    float r0 = t[3];
    float r1 = r0 + t[2];
    float r2 = r1 + t[1];
    float r3 = r2 + t[0];
    yc[0] = r3; yc[1] = r2; yc[2] = r1; yc[3] = r0;
    yc[4] = 0.f;
    float u0 = t[5];
    float u1 = u0 + t[6];
    float u2 = u1 + t[7];
    float u3 = u2 + t[8];
    yc[5] = u0; yc[6] = u1; yc[7] = u2; yc[8] = u3;

#pragma unroll
    for (int k = 0; k < 9; k++) {
        float y  = (float)w + yc[k];
        float tt = fminf(fmaxf(y * (1.f/256.f), 0.f), 1.f);
        g_py[(b*KK + k)*PIX + p] = tt * 255.f;
    }
}

// ----------------------------- K4: fused bilinear-sample + (K,1)-strided conv
__global__ void __launch_bounds__(512, 1)
k_main(const float* __restrict__ x,
       const float* __restrict__ wdsc,
       const float* __restrict__ bdsc) {
    extern __shared__ __align__(16) float sm[];
    float* Xs  = sm;                  // XSZ
    float* Ws  = Xs + XSZ;            // WSZ [k][ci][co], 16B-aligned (XSZ%4==0)
    float* sOs = Ws + WSZ;            // 8
    float* sOq = sOs + 8;             // 8

    int b  = blockIdx.z;
    int w0 = blockIdx.y * TW;
    int h0 = blockIdx.x * TH;
    int tid = threadIdx.x;
    int rbase = w0 - 5, cbase = h0 - 5;

    int hl = tid & 31, wl = tid >> 5;
    int w = w0 + wl, h = h0 + hl;

    // own-pixel py values -> registers (coalesced LDG)
    float pyr[KK];
#pragma unroll
    for (int k = 0; k < KK; k++)
        pyr[k] = g_py[(b*KK + k)*PIX + w*256 + h];

    // weights: [k][ci][co], co contiguous
    for (int i = tid; i < WSZ; i += 512) {
        int co = i & 31; int rest = i >> 5;
        int ci = rest & 31; int k = rest >> 5;
        Ws[i] = wdsc[(co*CC + ci)*KK + k];
    }
    // x tile with clamped halo
    const float* xb = x + b*CC*PIX;
    for (int i = tid; i < XSZ; i += 512) {
        int c = i % CCOLS; int rest = i / CCOLS;
        int r = rest % RROWS; int ci = rest / RROWS;
        int gr = min(max(rbase + r, 0), 255);
        int gc = min(max(cbase + c, 0), 255);
        Xs[i] = xb[ci*PIX + gr*256 + gc];
    }
    if (tid < 8) { sOs[tid] = 0.f; sOq[tid] = 0.f; }
    __syncthreads();

    u64 acc[16];
#pragma unroll
    for (int i = 0; i < 16; i++) acc[i] = 0ull;

#pragma unroll 1
    for (int k = 0; k < KK; k++) {
        float fx  = (float)(h + k - 4);
        float px  = fminf(fmaxf(fx * (1.f/256.f), 0.f), 1.f) * 255.f;
        float x0f = floorf(px);
        float wx  = px - x0f;
        int x0i = (int)x0f;
        int x1i = min(x0i + 1, 255);
        int cs0 = x0i - cbase, cs1 = x1i - cbase;

        float py  = pyr[k];
        float y0f = floorf(py);
        float wy  = py - y0f;
        int y0i = (int)y0f;
        int y1i = min(y0i + 1, 255);
        int rs0 = y0i - rbase, rs1 = y1i - rbase;

        float w00 = (1.f - wy)*(1.f - wx);
        float w01 = (1.f - wy)*wx;
        float w10 = wy*(1.f - wx);
        float w11 = wy*wx;

        int o00 = rs0*CCOLS + cs0, o01 = rs0*CCOLS + cs1;
        int o10 = rs1*CCOLS + cs0, o11 = rs1*CCOLS + cs1;

        const float* Wk = Ws + k*(CC*CC);
#pragma unroll 4
        for (int ci = 0; ci < CC; ci++) {
            const float* Xc = Xs + ci*(RROWS*CCOLS);
            float v = w00*Xc[o00];
            v = fmaf(w01, Xc[o01], v);
            v = fmaf(w10, Xc[o10], v);
            v = fmaf(w11, Xc[o11], v);
            u64 v2 = pack2(v);
            const ulonglong2* wp = (const ulonglong2*)(Wk + ci*CC);
#pragma unroll
            for (int j = 0; j < 8; j++) {
                ulonglong2 wv = wp[j];
                acc[2*j]   = ffma2(v2, wv.x, acc[2*j]);
                acc[2*j+1] = ffma2(v2, wv.y, acc[2*j+1]);
            }
        }
    }

    // store pre-GN output + accumulate GN stats (per 4-channel group)
    float* outp = g_pre + (b*CC)*PIX + w*256 + h;
    float s[8], q[8];
#pragma unroll
    for (int g = 0; g < 8; g++) { s[g] = 0.f; q[g] = 0.f; }
#pragma unroll
    for (int j = 0; j < 16; j++) {
        float v0, v1; unpack2(acc[j], v0, v1);
        v0 += __ldg(&bdsc[2*j]);
        v1 += __ldg(&bdsc[2*j+1]);
        outp[(2*j)*PIX]   = v0;
        outp[(2*j+1)*PIX] = v1;
        int g = j >> 1;
        s[g] += v0 + v1;
        q[g] += v0*v0 + v1*v1;
    }
#pragma unroll
    for (int g = 0; g < 8; g++) {
        float ss = s[g], qq = q[g];
#pragma unroll
        for (int off = 16; off; off >>= 1) {
            ss += __shfl_xor_sync(0xffffffffu, ss, off);
            qq += __shfl_xor_sync(0xffffffffu, qq, off);
        }
        if ((tid & 31) == 0) { atomicAdd(&sOs[g], ss); atomicAdd(&sOq[g], qq); }
    }
    __syncthreads();
    if (tid < 8) {
        atomicAdd(&g_sout[(b*8 + tid)*2 + 0], sOs[tid]);
        atomicAdd(&g_sout[(b*8 + tid)*2 + 1], sOq[tid]);
    }
}

// ---------------------------------------------- K2b: finalize final GN stats
__global__ void k_stats_out() {
    int t = threadIdx.x;
    if (t < BB*8) {
        float S = g_sout[t*2], Q = g_sout[t*2 + 1];
        float inv = 1.f / (4.f * (float)PIX);
        float mu  = S * inv;
        float var = Q * inv - mu*mu;
        g_mrout[t*2]     = mu;
        g_mrout[t*2 + 1] = rsqrtf(var + 1e-5f);
    }
}

// ------------------------------------------------------ K5: GN + ReLU -> out
__global__ void k_final(float* __restrict__ out,
                        const float* __restrict__ sc,
                        const float* __restrict__ bi) {
    int i4 = blockIdx.x*256 + threadIdx.x;
    int e  = i4 * 4;
    int c = (e >> 16) & 31;
    int b = e >> 21;
    int g = c >> 2;
    float mu = g_mrout[(b*8 + g)*2], rs = g_mrout[(b*8 + g)*2 + 1];
    float scv = sc[c], biv = bi[c];
    float4 v = *(const float4*)(g_pre + e);
    float4 o;
    o.x = fmaxf(fmaf((v.x - mu)*rs, scv, biv), 0.f);
    o.y = fmaxf(fmaf((v.y - mu)*rs, scv, biv), 0.f);
    o.z = fmaxf(fmaf((v.z - mu)*rs, scv, biv), 0.f);
    o.w = fmaxf(fmaf((v.w - mu)*rs, scv, biv), 0.f);
    *(float4*)(out + e) = o;
}

#define SMEM_MAIN ((XSZ + WSZ + 16) * (int)sizeof(float))

extern "C" void kernel_launch(void* const* d_in, const int* in_sizes, int n_in,
                              void* d_out, int out_size) {
    const float* x       = (const float*)d_in[0];
    const float* w_off   = (const float*)d_in[1];
    const float* b_off   = (const float*)d_in[2];
    const float* gos     = (const float*)d_in[3];
    const float* gob     = (const float*)d_in[4];
    const float* wdsc    = (const float*)d_in[5];
    const float* bdsc    = (const float*)d_in[6];
    const float* gsc     = (const float*)d_in[7];
    const float* gbi     = (const float*)d_in[8];
    float* out = (float*)d_out;

    cudaFuncSetAttribute(k_main, cudaFuncAttributeMaxDynamicSharedMemorySize, SMEM_MAIN);

    k_zero<<<1, 128>>>();
    k_conv_off<<<dim3(PIX/256, BB), 256>>>(x, w_off, b_off);
    k_stats_off<<<1, 32>>>();
    k_py<<<dim3(PIX/256, BB), 256>>>(gos, gob);
    k_main<<<dim3(HH/TH, WW/TW, BB), 512, SMEM_MAIN>>>(x, wdsc, bdsc);
    k_stats_out<<<1, 32>>>();
    k_final<<<(BB*CC*PIX)/1024, 256>>>(out, gsc, gbi);
}

// round 5
// speedup vs baseline: 1.4341x; 1.4341x over previous
#include <cuda_runtime.h>
#include <cuda_bf16.h>
#include <math.h>

// Problem constants
#define BB 4
#define CC 32
#define WW 256
#define HH 256
#define KK 9
#define OC_OFF 10
#define PIX (WW*HH)

// k_main tile: 16 w-rows x 32 h-cols, 256 threads, 2 px/thread
#define TWM 16
#define THM 32
#define RROWS 26           // TWM + 10
#define CCOLS 42           // THM + 10
#define NCI 8              // ci per chunk
#define XCH (NCI*RROWS*CCOLS)   // 8736 floats per chunk
#define WSZ (KK*CC*CC)          // 9216

typedef unsigned long long u64;

__device__ __forceinline__ u64 ffma2(u64 a, u64 b, u64 c) {
    u64 d;
    asm("fma.rn.f32x2 %0, %1, %2, %3;" : "=l"(d) : "l"(a), "l"(b), "l"(c));
    return d;
}
__device__ __forceinline__ u64 pack2(float v) {
    u64 d; unsigned u = __float_as_uint(v);
    asm("mov.b64 %0, {%1, %1};" : "=l"(d) : "r"(u));
    return d;
}
__device__ __forceinline__ void unpack2(u64 in, float& lo, float& hi) {
    unsigned a, b;
    asm("mov.b64 {%0, %1}, %2;" : "=r"(a), "=r"(b) : "l"(in));
    lo = __uint_as_float(a); hi = __uint_as_float(b);
}

// Scratch
__device__ float g_off[BB*OC_OFF*PIX];
__device__ float g_py [BB*KK*PIX];
__device__ float g_pre[BB*CC*PIX];
__device__ float g_soff[BB*5*2];
__device__ float g_mroff[BB*5*2];
__device__ float g_sout[BB*8*2];
__device__ float g_mrout[BB*8*2];

// ---------------------------------------------------------------- zero stats
__global__ void k_zero() {
    int t = threadIdx.x;
    if (t < BB*5*2) g_soff[t] = 0.f;
    if (t < BB*8*2) g_sout[t] = 0.f;
}

// ---------------------- K1: 3x3 conv, 32 -> 10 ch, 4 pixels (w-rows) / thread
__global__ void __launch_bounds__(256, 2)
k_conv_off(const float* __restrict__ x,
           const float* __restrict__ w_off,
           const float* __restrict__ b_off) {
    __shared__ __align__(8) float ws[CC*9*OC_OFF];   // [ci][tap][10]
    __shared__ float s_sum[5], s_sq[5];
    int b   = blockIdx.y;
    int wb  = blockIdx.x * 4;
    int tid = threadIdx.x;
    int h   = tid;

    for (int i = tid; i < CC*9*OC_OFF; i += 256) {
        int o = i % OC_OFF; int rest = i / OC_OFF;
        int tap = rest % 9; int ci = rest / 9;
        int dy = tap / 3, dx = tap % 3;
        ws[i] = w_off[((o*CC + ci)*3 + dy)*3 + dx];
    }
    if (tid < 5) { s_sum[tid] = 0.f; s_sq[tid] = 0.f; }
    __syncthreads();

    u64 acc[4][5];
    const u64* b2 = (const u64*)b_off;
#pragma unroll
    for (int p = 0; p < 4; p++)
#pragma unroll
        for (int j = 0; j < 5; j++) acc[p][j] = b2[j];

    const float* xb = x + b*CC*PIX;
#pragma unroll 1
    for (int ci = 0; ci < CC; ci++) {
        const float* xc = xb + ci*PIX;
        u64 v2[6][3];
#pragma unroll
        for (int rr = 0; rr < 6; rr++) {
            int r = wb - 1 + rr;
            bool rok = (unsigned)r < 256u;
#pragma unroll
            for (int dx = 0; dx < 3; dx++) {
                int c = h + dx - 1;
                float v = (rok && (unsigned)c < 256u) ? xc[r*256 + c] : 0.f;
                v2[rr][dx] = pack2(v);
            }
        }
#pragma unroll
        for (int tap = 0; tap < 9; tap++) {
            int dy = tap / 3, dx = tap % 3;
            const u64* wp = (const u64*)&ws[(ci*9 + tap)*OC_OFF];
            u64 w0 = wp[0], w1 = wp[1], w2 = wp[2], w3 = wp[3], w4 = wp[4];
#pragma unroll
            for (int p = 0; p < 4; p++) {
                u64 vv = v2[dy + p][dx];
                acc[p][0] = ffma2(vv, w0, acc[p][0]);
                acc[p][1] = ffma2(vv, w1, acc[p][1]);
                acc[p][2] = ffma2(vv, w2, acc[p][2]);
                acc[p][3] = ffma2(vv, w3, acc[p][3]);
                acc[p][4] = ffma2(vv, w4, acc[p][4]);
            }
        }
    }

    float s[5], q[5];
#pragma unroll
    for (int j = 0; j < 5; j++) { s[j] = 0.f; q[j] = 0.f; }
#pragma unroll
    for (int p = 0; p < 4; p++) {
        int w = wb + p;
        float* outp = g_off + b*OC_OFF*PIX + w*256 + h;
#pragma unroll
        for (int j = 0; j < 5; j++) {
            float v0, v1; unpack2(acc[p][j], v0, v1);
            outp[(2*j)*PIX]   = v0;
            outp[(2*j+1)*PIX] = v1;
            s[j] += v0 + v1;
            q[j] += v0*v0 + v1*v1;
        }
    }
#pragma unroll
    for (int j = 0; j < 5; j++) {
        float ss = s[j], qq = q[j];
#pragma unroll
        for (int off = 16; off; off >>= 1) {
            ss += __shfl_xor_sync(0xffffffffu, ss, off);
            qq += __shfl_xor_sync(0xffffffffu, qq, off);
        }
        if ((tid & 31) == 0) { atomicAdd(&s_sum[j], ss); atomicAdd(&s_sq[j], qq); }
    }
    __syncthreads();
    if (tid < 5) {
        atomicAdd(&g_soff[(b*5 + tid)*2 + 0], s_sum[tid]);
        atomicAdd(&g_soff[(b*5 + tid)*2 + 1], s_sq[tid]);
    }
}

// --------------------------------------------- K2a: finalize offset GN stats
__global__ void k_stats_off() {
    int t = threadIdx.x;
    if (t < BB*5) {
        float S = g_soff[t*2], Q = g_soff[t*2 + 1];
        float inv = 1.f / (2.f * (float)PIX);
        float mu  = S * inv;
        float var = Q * inv - mu*mu;
        g_mroff[t*2]     = mu;
        g_mroff[t*2 + 1] = rsqrtf(var + 1e-5f);
    }
}

// --------------------- K3: GN + tanh + cumsum -> sampling coordinate field py
__global__ void k_py(const float* __restrict__ sc, const float* __restrict__ bi) {
    int b = blockIdx.y;
    int p = blockIdx.x*256 + threadIdx.x;
    int w = p >> 8;

    float t[9];
#pragma unroll
    for (int c = 0; c < 9; c++) {
        float v  = g_off[(b*OC_OFF + c)*PIX + p];
        int   g  = c >> 1;
        float mu = g_mroff[(b*5 + g)*2], rs = g_mroff[(b*5 + g)*2 + 1];
        t[c] = tanhf(fmaf((v - mu)*rs, sc[c], bi[c]));
    }
    float yc[9];
    float r0 = t[3];
    float r1 = r0 + t[2];
    float r2 = r1 + t[1];
    float r3 = r2 + t[0];
    yc[0] = r3; yc[1] = r2; yc[2] = r1; yc[3] = r0;
    yc[4] = 0.f;
    float u0 = t[5];
    float u1 = u0 + t[6];
    float u2 = u1 + t[7];
    float u3 = u2 + t[8];
    yc[5] = u0; yc[6] = u1; yc[7] = u2; yc[8] = u3;

#pragma unroll
    for (int k = 0; k < 9; k++) {
        float y  = (float)w + yc[k];
        float tt = fminf(fmaxf(y * (1.f/256.f), 0.f), 1.f);
        g_py[(b*KK + k)*PIX + p] = tt * 255.f;
    }
}

// ------------- K4: fused bilinear-sample + (K,1)-strided conv, 2 px / thread
__global__ void __launch_bounds__(256, 2)
k_main(const float* __restrict__ x,
       const float* __restrict__ wdsc,
       const float* __restrict__ bdsc) {
    extern __shared__ __align__(16) float sm[];
    float* Xs  = sm;                  // XCH (one ci-chunk)
    float* Ws  = Xs + XCH;            // WSZ [k][ci][co]
    float* sOs = Ws + WSZ;            // 8
    float* sOq = sOs + 8;             // 8

    int b  = blockIdx.z;
    int w0 = blockIdx.y * TWM;
    int h0 = blockIdx.x * THM;
    int tid = threadIdx.x;
    int rbase = w0 - 5, cbase = h0 - 5;

    int hl = tid & 31, wl = tid >> 5;      // wl in 0..7
    int h = h0 + hl;
    int wA = w0 + wl, wB = w0 + wl + 8;

    // weights: [k][ci][co], co contiguous
    for (int i = tid; i < WSZ; i += 256) {
        int co = i & 31; int rest = i >> 5;
        int ci = rest & 31; int k = rest >> 5;
        Ws[i] = wdsc[(co*CC + ci)*KK + k];
    }
    if (tid < 8) { sOs[tid] = 0.f; sOq[tid] = 0.f; }

    u64 accA[16], accB[16];
#pragma unroll
    for (int i = 0; i < 16; i++) { accA[i] = 0ull; accB[i] = 0ull; }

    const float* xb = x + b*CC*PIX;
    const float* pyb = g_py + b*KK*PIX;

#pragma unroll 1
    for (int chunk = 0; chunk < 4; chunk++) {
        __syncthreads();
        // load 8-channel X chunk with clamped halo
        for (int i = tid; i < XCH; i += 256) {
            int c = i % CCOLS; int rest = i / CCOLS;
            int r = rest % RROWS; int ci8 = rest / RROWS;
            int gr = min(max(rbase + r, 0), 255);
            int gc = min(max(cbase + c, 0), 255);
            Xs[i] = xb[(chunk*NCI + ci8)*PIX + gr*256 + gc];
        }
        __syncthreads();

#pragma unroll 1
        for (int k = 0; k < KK; k++) {
            // column geometry (shared by both pixels: same h)
            float fx  = (float)(h + k - 4);
            float px  = fminf(fmaxf(fx * (1.f/256.f), 0.f), 1.f) * 255.f;
            float x0f = floorf(px);
            float wx  = px - x0f;
            int x0i = (int)x0f;
            int x1i = min(x0i + 1, 255);
            int cs0 = x0i - cbase, cs1 = x1i - cbase;

            // row geometry per pixel
            float pyA = __ldg(&pyb[k*PIX + wA*256 + h]);
            float pyB = __ldg(&pyb[k*PIX + wB*256 + h]);

            float yA0 = floorf(pyA); float wyA = pyA - yA0;
            int yA0i = (int)yA0; int yA1i = min(yA0i + 1, 255);
            int rsA0 = yA0i - rbase, rsA1 = yA1i - rbase;
            float yB0 = floorf(pyB); float wyB = pyB - yB0;
            int yB0i = (int)yB0; int yB1i = min(yB0i + 1, 255);
            int rsB0 = yB0i - rbase, rsB1 = yB1i - rbase;

            float a00 = (1.f - wyA)*(1.f - wx), a01 = (1.f - wyA)*wx;
            float a10 = wyA*(1.f - wx),        a11 = wyA*wx;
            float b00 = (1.f - wyB)*(1.f - wx), b01 = (1.f - wyB)*wx;
            float b10 = wyB*(1.f - wx),        b11 = wyB*wx;

            int oA00 = rsA0*CCOLS + cs0, oA01 = rsA0*CCOLS + cs1;
            int oA10 = rsA1*CCOLS + cs0, oA11 = rsA1*CCOLS + cs1;
            int oB00 = rsB0*CCOLS + cs0, oB01 = rsB0*CCOLS + cs1;
            int oB10 = rsB1*CCOLS + cs0, oB11 = rsB1*CCOLS + cs1;

            const float* WkBase = Ws + (k*CC + chunk*NCI)*CC;
#pragma unroll
            for (int ci8 = 0; ci8 < NCI; ci8++) {
                const float* Xc = Xs + ci8*(RROWS*CCOLS);
                float vA = a00*Xc[oA00];
                vA = fmaf(a01, Xc[oA01], vA);
                vA = fmaf(a10, Xc[oA10], vA);
                vA = fmaf(a11, Xc[oA11], vA);
                float vB = b00*Xc[oB00];
                vB = fmaf(b01, Xc[oB01], vB);
                vB = fmaf(b10, Xc[oB10], vB);
                vB = fmaf(b11, Xc[oB11], vB);
                u64 v2A = pack2(vA);
                u64 v2B = pack2(vB);
                const u64* wp = (const u64*)(WkBase + ci8*CC);
#pragma unroll
                for (int j = 0; j < 16; j++) {
                    u64 wv = wp[j];
                    accA[j] = ffma2(v2A, wv, accA[j]);
                    accB[j] = ffma2(v2B, wv, accB[j]);
                }
            }
        }
    }

    // store pre-GN output + accumulate GN stats (per 4-channel group)
    float s[8], q[8];
#pragma unroll
    for (int g = 0; g < 8; g++) { s[g] = 0.f; q[g] = 0.f; }
    float* outA = g_pre + (b*CC)*PIX + wA*256 + h;
    float* outB = g_pre + (b*CC)*PIX + wB*256 + h;
#pragma unroll
    for (int j = 0; j < 16; j++) {
        float bl = __ldg(&bdsc[2*j]), bh = __ldg(&bdsc[2*j+1]);
        float v0, v1; unpack2(accA[j], v0, v1);
        v0 += bl; v1 += bh;
        outA[(2*j)*PIX]   = v0;
        outA[(2*j+1)*PIX] = v1;
        int g = j >> 1;
        s[g] += v0 + v1;
        q[g] += v0*v0 + v1*v1;
        float u0, u1; unpack2(accB[j], u0, u1);
        u0 += bl; u1 += bh;
        outB[(2*j)*PIX]   = u0;
        outB[(2*j+1)*PIX] = u1;
        s[g] += u0 + u1;
        q[g] += u0*u0 + u1*u1;
    }
#pragma unroll
    for (int g = 0; g < 8; g++) {
        float ss = s[g], qq = q[g];
#pragma unroll
        for (int off = 16; off; off >>= 1) {
            ss += __shfl_xor_sync(0xffffffffu, ss, off);
            qq += __shfl_xor_sync(0xffffffffu, qq, off);
        }
        if ((tid & 31) == 0) { atomicAdd(&sOs[g], ss); atomicAdd(&sOq[g], qq); }
    }
    __syncthreads();
    if (tid < 8) {
        atomicAdd(&g_sout[(b*8 + tid)*2 + 0], sOs[tid]);
        atomicAdd(&g_sout[(b*8 + tid)*2 + 1], sOq[tid]);
    }
}

// ---------------------------------------------- K2b: finalize final GN stats
__global__ void k_stats_out() {
    int t = threadIdx.x;
    if (t < BB*8) {
        float S = g_sout[t*2], Q = g_sout[t*2 + 1];
        float inv = 1.f / (4.f * (float)PIX);
        float mu  = S * inv;
        float var = Q * inv - mu*mu;
        g_mrout[t*2]     = mu;
        g_mrout[t*2 + 1] = rsqrtf(var + 1e-5f);
    }
}

// ------------------------------------------------------ K5: GN + ReLU -> out
__global__ void k_final(float* __restrict__ out,
                        const float* __restrict__ sc,
                        const float* __restrict__ bi) {
    int i4 = blockIdx.x*256 + threadIdx.x;
    int e  = i4 * 4;
    int c = (e >> 16) & 31;
    int b = e >> 21;
    int g = c >> 2;
    float mu = g_mrout[(b*8 + g)*2], rs = g_mrout[(b*8 + g)*2 + 1];
    float scv = sc[c], biv = bi[c];
    float4 v = *(const float4*)(g_pre + e);
    float4 o;
    o.x = fmaxf(fmaf((v.x - mu)*rs, scv, biv), 0.f);
    o.y = fmaxf(fmaf((v.y - mu)*rs, scv, biv), 0.f);
    o.z = fmaxf(fmaf((v.z - mu)*rs, scv, biv), 0.f);
    o.w = fmaxf(fmaf((v.w - mu)*rs, scv, biv), 0.f);
    *(float4*)(out + e) = o;
}

#define SMEM_MAIN ((XCH + WSZ + 16) * (int)sizeof(float))

extern "C" void kernel_launch(void* const* d_in, const int* in_sizes, int n_in,
                              void* d_out, int out_size) {
    const float* x       = (const float*)d_in[0];
    const float* w_off   = (const float*)d_in[1];
    const float* b_off   = (const float*)d_in[2];
    const float* gos     = (const float*)d_in[3];
    const float* gob     = (const float*)d_in[4];
    const float* wdsc    = (const float*)d_in[5];
    const float* bdsc    = (const float*)d_in[6];
    const float* gsc     = (const float*)d_in[7];
    const float* gbi     = (const float*)d_in[8];
    float* out = (float*)d_out;

    cudaFuncSetAttribute(k_main, cudaFuncAttributeMaxDynamicSharedMemorySize, SMEM_MAIN);

    k_zero<<<1, 128>>>();
    k_conv_off<<<dim3(WW/4, BB), 256>>>(x, w_off, b_off);
    k_stats_off<<<1, 32>>>();
    k_py<<<dim3(PIX/256, BB), 256>>>(gos, gob);
    k_main<<<dim3(HH/THM, WW/TWM, BB), 256, SMEM_MAIN>>>(x, wdsc, bdsc);
    k_stats_out<<<1, 32>>>();
    k_final<<<(BB*CC*PIX)/1024, 256>>>(out, gsc, gbi);
}